// round 13
// baseline (speedup 1.0000x reference)
#include <cuda_runtime.h>

// Problem constants (fixed by the dataset instance)
#define W_ 256
#define PLANE 65536
#define THREADS 256
// tile = 16 patches (64c x 4r x 64w) -> 2048 tiles, one block each.
// KEY CHANGE: no register-resident tile. x is read 3x (passes B,C hit L2),
// freeing registers -> 4 blocks/SM -> 4 independent chains keep DRAM fed.

__device__ __forceinline__ float sigm(float x) {
    return 1.0f / (1.0f + __expf(-x));
}

__global__ __launch_bounds__(THREADS, 4)
void ciam_3pass_kernel(const float* __restrict__ x,
                       const float* __restrict__ fc_w,
                       const float* __restrict__ fc_b,
                       const float* __restrict__ c1w,
                       const float* __restrict__ c1b,
                       const float* __restrict__ c2w,
                       const float* __restrict__ c2b,
                       float* __restrict__ out)
{
    // ---- block / thread decomposition ----
    const int blk = blockIdx.x;          // 0..2047
    const int pwg = blk & 3;             // 16-patch group along W
    const int ph  = (blk >> 2) & 63;     // patch row
    const int b   = blk >> 8;            // batch

    const int t  = threadIdx.x;
    const int p  = t & 15;               // patch
    const int r  = (t >> 4) & 3;         // row within patch
    const int cb = t >> 6;               // channel base 0..3 (c = cb + 4k, k<16)
    const int rp = t & 63;               // (r, patch)

    // ---- shared memory (~43 KB) ----
    __shared__ float wS[64 * 68];        // fc_w rows, stride 68
    __shared__ float fcbS[64];
    __shared__ float mxT[1024];          // channel maxes [c][p] (p contiguous)
    __shared__ float msm[1024];          // channel attention m[c][p]
    __shared__ float g1s[256];           // g1[(r,p)*4 + px]
    __shared__ float g2s[16];
    __shared__ float uni[4160];          // pm[4][1040] -> gsum/gmax/p2s/p2m

    // ---- scalar weights ----
    const float c1w0 = __ldg(c1w), c1w1 = __ldg(c1w + 1), c1b0 = __ldg(c1b);
    const float c2w0 = __ldg(c2w), c2w1 = __ldg(c2w + 1), c2b0 = __ldg(c2b);

    const size_t plane = PLANE;
    const float* xb = x + (size_t)b * 64 * plane;
    float* ob = out + (size_t)b * 64 * plane;
    const int rowbase = (ph * 4 + r) * W_ + pwg * 64 + p * 4;
    const float* xt = xb + rowbase;      // + c*plane per channel

    // ---- stage fc_w -> smem (stride 68), fc_b -> smem ----
    #pragma unroll
    for (int i = 0; i < 4; i++) {
        const int j  = t + 256 * i;      // float4 chunk id, 0..1023
        const int c  = j >> 4;
        const int k4 = j & 15;
        *(float4*)(wS + c * 68 + k4 * 4) = *(const float4*)(fc_w + c * 64 + k4 * 4);
    }
    if (t < 64) fcbS[t] = fc_b[t];

    // ================= PASS A: read tile (DRAM), channel max, matvec =================
    float* pm = uni;                     // [r][c*16+p], row stride 1040
    #pragma unroll
    for (int k = 0; k < 16; k++) {
        const float4 a = *(const float4*)(xt + (size_t)(cb + 4 * k) * plane);
        pm[r * 1040 + (cb + 4 * k) * 16 + p] =
            fmaxf(fmaxf(a.x, a.y), fmaxf(a.z, a.w));
    }
    __syncthreads();

    // reduce over r -> mxT (float4 form)
    {
        const int id4 = t * 4;           // 0..1020, covers c*16+p
        float4 a0 = *(const float4*)(pm + id4);
        float4 a1 = *(const float4*)(pm + 1040 + id4);
        float4 a2 = *(const float4*)(pm + 2080 + id4);
        float4 a3 = *(const float4*)(pm + 3120 + id4);
        float4 mr;
        mr.x = fmaxf(fmaxf(a0.x, a1.x), fmaxf(a2.x, a3.x));
        mr.y = fmaxf(fmaxf(a0.y, a1.y), fmaxf(a2.y, a3.y));
        mr.z = fmaxf(fmaxf(a0.z, a1.z), fmaxf(a2.z, a3.z));
        mr.w = fmaxf(fmaxf(a0.w, a1.w), fmaxf(a2.w, a3.w));
        *(float4*)(mxT + id4) = mr;
    }
    __syncthreads();

    // matvec: m[c][p] = sigm(w[c].mx[:,p] + b[c]); 4 outputs/thread
    {
        const int c  = t >> 2;           // 0..63
        const int pq = (t & 3) * 4;      // 0,4,8,12
        float4 acc = make_float4(0.f, 0.f, 0.f, 0.f);
        #pragma unroll
        for (int kc = 0; kc < 16; kc++) {
            const float4 w4 = *(const float4*)(wS + c * 68 + kc * 4);
            const float4 m0 = *(const float4*)(mxT + (kc * 4 + 0) * 16 + pq);
            const float4 m1 = *(const float4*)(mxT + (kc * 4 + 1) * 16 + pq);
            acc.x += w4.x * m0.x + w4.y * m1.x;
            acc.y += w4.x * m0.y + w4.y * m1.y;
            acc.z += w4.x * m0.z + w4.y * m1.z;
            acc.w += w4.x * m0.w + w4.y * m1.w;
            const float4 m2 = *(const float4*)(mxT + (kc * 4 + 2) * 16 + pq);
            const float4 m3 = *(const float4*)(mxT + (kc * 4 + 3) * 16 + pq);
            acc.x += w4.z * m2.x + w4.w * m3.x;
            acc.y += w4.z * m2.y + w4.w * m3.y;
            acc.z += w4.z * m2.z + w4.w * m3.z;
            acc.w += w4.z * m2.w + w4.w * m3.w;
        }
        const float bc = fcbS[c];
        float4 mres;
        mres.x = sigm(acc.x + bc);
        mres.y = sigm(acc.y + bc);
        mres.z = sigm(acc.z + bc);
        mres.w = sigm(acc.w + bc);
        *(float4*)(msm + c * 16 + pq) = mres;
    }
    __syncthreads();

    // ================= PASS B: re-read (L2), apply m transiently, partials =================
    float4 ps  = make_float4(0.f, 0.f, 0.f, 0.f);
    float4 pmx = make_float4(-3.4e38f, -3.4e38f, -3.4e38f, -3.4e38f);
    #pragma unroll
    for (int k = 0; k < 16; k++) {
        float4 a = *(const float4*)(xt + (size_t)(cb + 4 * k) * plane);
        const float m = msm[(cb + 4 * k) * 16 + p];
        a.x *= m; a.y *= m; a.z *= m; a.w *= m;
        ps.x += a.x; ps.y += a.y; ps.z += a.z; ps.w += a.w;
        pmx.x = fmaxf(pmx.x, a.x); pmx.y = fmaxf(pmx.y, a.y);
        pmx.z = fmaxf(pmx.z, a.z); pmx.w = fmaxf(pmx.w, a.w);
    }
    float* gsum = uni;                   // [cb][rp*4+px] : 1024 floats
    float* gmax = uni + 1024;
    *(float4*)(gsum + cb * 256 + rp * 4) = ps;
    *(float4*)(gmax + cb * 256 + rp * 4) = pmx;
    __syncthreads();

    // g1 per (patch,pixel) AND g2 partials (fused algebra: g1>0 so max commutes)
    float* p2s = uni + 2048;             // 256 floats, indexed by t = (r,p,px)
    float* p2m = uni + 2304;
    {
        float s  = gsum[t] + gsum[256 + t] + gsum[512 + t] + gsum[768 + t];
        float mx = fmaxf(fmaxf(gmax[t], gmax[256 + t]), fmaxf(gmax[512 + t], gmax[768 + t]));
        const float g1 = sigm(c1w0 * (s * (1.0f / 64.0f)) + c1w1 * mx + c1b0);
        g1s[t] = g1;
        p2s[t] = g1 * s;
        p2m[t] = g1 * mx;
    }
    __syncthreads();

    // g2 per patch
    if (t < 16) {
        float s = 0.f, mx = -3.4e38f;
        #pragma unroll
        for (int rr = 0; rr < 4; rr++) {
            #pragma unroll
            for (int px = 0; px < 4; px++) {
                const int id = rr * 64 + t * 4 + px;
                s += p2s[id];
                mx = fmaxf(mx, p2m[id]);
            }
        }
        g2s[t] = sigm(c2w0 * (s * (1.0f / 1024.0f)) + c2w1 * mx + c2b0);
    }
    __syncthreads();

    // ================= PASS C: re-read (L2), y = x * m * (g1*g2), store =================
    const float4 g1v = *(const float4*)(g1s + rp * 4);
    const float g2 = g2s[p];
    const float4 gg = make_float4(g1v.x * g2, g1v.y * g2, g1v.z * g2, g1v.w * g2);
    #pragma unroll
    for (int k = 0; k < 16; k++) {
        float4 a = *(const float4*)(xt + (size_t)(cb + 4 * k) * plane);
        const float m = msm[(cb + 4 * k) * 16 + p];
        a.x *= m * gg.x; a.y *= m * gg.y; a.z *= m * gg.z; a.w *= m * gg.w;
        *(float4*)(ob + (size_t)(cb + 4 * k) * plane + rowbase) = a;
    }
}

extern "C" void kernel_launch(void* const* d_in, const int* in_sizes, int n_in,
                              void* d_out, int out_size) {
    const float* x    = (const float*)d_in[0];
    const float* fc_w = (const float*)d_in[1];
    const float* fc_b = (const float*)d_in[2];
    const float* c1w  = (const float*)d_in[3];
    const float* c1b  = (const float*)d_in[4];
    const float* c2w  = (const float*)d_in[5];
    const float* c2b  = (const float*)d_in[6];
    float* out = (float*)d_out;

    // 2048 blocks: 8 batches x 64 patch-rows x 4 groups of 16 patches
    ciam_3pass_kernel<<<2048, THREADS>>>(x, fc_w, fc_b, c1w, c1b, c2w, c2b, out);
}

// round 14
// speedup vs baseline: 1.4036x; 1.4036x over previous
#include <cuda_runtime.h>

// Problem constants (fixed by the dataset instance)
#define Bc 8
#define Cc 64
#define Hc 256
#define Wc 256
// size = 4 -> 64x64 patches of 4x4; each block handles 16 patches
#define THREADS 256

__device__ __forceinline__ float sigm(float x) {
    return 1.0f / (1.0f + __expf(-x));
}

__global__ __launch_bounds__(THREADS, 2)
void ciam_fused_kernel(const float* __restrict__ x,
                       const float* __restrict__ fc_w,
                       const float* __restrict__ fc_b,
                       const float* __restrict__ c1w,
                       const float* __restrict__ c1b,
                       const float* __restrict__ c2w,
                       const float* __restrict__ c2b,
                       float* __restrict__ out)
{
    // ---- block / thread decomposition ----
    const int blk = blockIdx.x;          // 0..2047
    const int pwg = blk & 3;             // 16-patch group along W
    const int ph  = (blk >> 2) & 63;     // patch row
    const int b   = blk >> 8;            // batch

    const int t     = threadIdx.x;
    const int patch = t & 15;            // local patch id (pw = pwg*16 + patch)
    const int r     = (t >> 4) & 3;      // row within patch
    const int cb    = t >> 6;            // channel base (c = cb + 4k)

    // ---- shared memory (~43.3 KB) ----
    __shared__ float wS[64 * 68];        // fc_w rows, stride 68 (16B-aligned, banks 4c)
    __shared__ float mxT[64 * 16];       // per-patch channel maxes, k-major [k][p]
    __shared__ float msm[64 * 16];       // channel-attention m[c][p], p contiguous
    __shared__ float g1s[64 * 4];        // g1[(r,patch)][px]
    __shared__ float fcbS[64];
    __shared__ float g2s[16];
    __shared__ float uni[4224];          // pm[4r][64c][16p] (row stride 1040) -> gsum/gmax/p2s/p2m

    // ---- scalar weights ----
    const float c1w0 = __ldg(c1w), c1w1 = __ldg(c1w + 1), c1b0 = __ldg(c1b);
    const float c2w0 = __ldg(c2w), c2w1 = __ldg(c2w + 1), c2b0 = __ldg(c2b);

    // ---- load tile into registers (16 x float4, coalesced) ----
    const size_t plane = (size_t)Hc * Wc;
    const float* xb = x + (size_t)b * Cc * plane;
    float* ob = out + (size_t)b * Cc * plane;
    const int rowbase = (ph * 4 + r) * Wc + pwg * 64 + patch * 4;

    float4 v[16];
    #pragma unroll
    for (int k = 0; k < 16; k++) {
        const int c = cb + 4 * k;
        v[k] = *(const float4*)(xb + (size_t)c * plane + rowbase);
    }

    // ---- stage fc_w -> smem (stride 68), fc_b -> smem ----
    #pragma unroll
    for (int i = 0; i < 4; i++) {
        const int j  = t + 256 * i;      // float4 chunk id, 0..1023
        const int c  = j >> 4;
        const int k4 = j & 15;
        float4 wv = *(const float4*)(fc_w + c * 64 + k4 * 4);
        *(float4*)(wS + c * 68 + k4 * 4) = wv;
    }
    if (t < 64) fcbS[t] = fc_b[t];

    // ---- per-(c, r, patch) row max -> pm (row stride 1040: conflict-free) ----
    float* pm = uni;                     // [r][c][p] = r*1040 + c*16 + p
    #pragma unroll
    for (int k = 0; k < 16; k++) {
        float4 a = v[k];
        float rm = fmaxf(fmaxf(a.x, a.y), fmaxf(a.z, a.w));
        pm[r * 1040 + (cb + 4 * k) * 16 + patch] = rm;
    }
    __syncthreads();

    // ---- reduce over r -> mxT[k][p] (k-major) ----
    {
        const int p  = t & 15;
        const int cB = t >> 4;           // 0..15
        #pragma unroll
        for (int j = 0; j < 4; j++) {
            const int c = cB + 16 * j;   // conflict-free: addr = c*16+p, c in {cB, cB+16,..}
            float m0 = pm[0 * 1040 + c * 16 + p];
            m0 = fmaxf(m0, pm[1 * 1040 + c * 16 + p]);
            m0 = fmaxf(m0, pm[2 * 1040 + c * 16 + p]);
            m0 = fmaxf(m0, pm[3 * 1040 + c * 16 + p]);
            mxT[c * 16 + p] = m0;        // mxT[k][p] with k == c index of the max vector
        }
    }
    __syncthreads();

    // ---- matvec: m[c][p] = sigmoid(sum_k w[c][k]*mx[k][p] + b[c]) ----
    // thread: c = t>>2 (one row), pq = t&3 (one float4 of patches)
    {
        const int c  = t >> 2;
        const int pq = t & 3;
        float4 acc = make_float4(0.f, 0.f, 0.f, 0.f);
        #pragma unroll
        for (int kc = 0; kc < 16; kc++) {
            const float4 w4 = *(const float4*)(wS + c * 68 + kc * 4);   // 1 wf/warp
            const float4 m0 = *(const float4*)(mxT + (kc * 4 + 0) * 16 + pq * 4);
            const float4 m1 = *(const float4*)(mxT + (kc * 4 + 1) * 16 + pq * 4);
            const float4 m2 = *(const float4*)(mxT + (kc * 4 + 2) * 16 + pq * 4);
            const float4 m3 = *(const float4*)(mxT + (kc * 4 + 3) * 16 + pq * 4);
            acc.x += w4.x * m0.x + w4.y * m1.x + w4.z * m2.x + w4.w * m3.x;
            acc.y += w4.x * m0.y + w4.y * m1.y + w4.z * m2.y + w4.w * m3.y;
            acc.z += w4.x * m0.z + w4.y * m1.z + w4.z * m2.z + w4.w * m3.z;
            acc.w += w4.x * m0.w + w4.y * m1.w + w4.z * m2.w + w4.w * m3.w;
        }
        const float bc = fcbS[c];
        float4 mres;
        mres.x = sigm(acc.x + bc);
        mres.y = sigm(acc.y + bc);
        mres.z = sigm(acc.z + bc);
        mres.w = sigm(acc.w + bc);
        *(float4*)(msm + c * 16 + pq * 4) = mres;
    }
    __syncthreads();

    // ---- apply channel attention; per-(patch,pixel) partials over 16 channels ----
    float4 ps  = make_float4(0.f, 0.f, 0.f, 0.f);
    float4 pmx = make_float4(-3.4e38f, -3.4e38f, -3.4e38f, -3.4e38f);
    #pragma unroll
    for (int k = 0; k < 16; k++) {
        const float m = msm[(cb + 4 * k) * 16 + patch];
        v[k].x *= m; v[k].y *= m; v[k].z *= m; v[k].w *= m;
        ps.x += v[k].x; ps.y += v[k].y; ps.z += v[k].z; ps.w += v[k].w;
        pmx.x = fmaxf(pmx.x, v[k].x); pmx.y = fmaxf(pmx.y, v[k].y);
        pmx.z = fmaxf(pmx.z, v[k].z); pmx.w = fmaxf(pmx.w, v[k].w);
    }
    float* gsum = uni;                   // [cb][rp][px] : cb*256 + rp*4 + px
    float* gmax = uni + 1024;
    const int rp = t & 63;               // (r, patch)
    *(float4*)(gsum + cb * 256 + rp * 4) = ps;
    *(float4*)(gmax + cb * 256 + rp * 4) = pmx;
    __syncthreads();

    // ---- g1 per (patch, pixel): reduce over the 4 channel-base groups ----
    {
        float s  = gsum[t] + gsum[256 + t] + gsum[512 + t] + gsum[768 + t];
        float mx = fmaxf(fmaxf(gmax[t], gmax[256 + t]), fmaxf(gmax[512 + t], gmax[768 + t]));
        g1s[t] = sigm(c1w0 * (s * (1.0f / 64.0f)) + c1w1 * mx + c1b0);
    }
    __syncthreads();

    // ---- apply g1; per-patch partials over this thread's 64 values ----
    const float4 g1v = *(const float4*)(g1s + rp * 4);
    float s2 = 0.f, m2 = -3.4e38f;
    #pragma unroll
    for (int k = 0; k < 16; k++) {
        v[k].x *= g1v.x; v[k].y *= g1v.y; v[k].z *= g1v.z; v[k].w *= g1v.w;
        s2 += v[k].x + v[k].y + v[k].z + v[k].w;
        m2 = fmaxf(m2, fmaxf(fmaxf(v[k].x, v[k].y), fmaxf(v[k].z, v[k].w)));
    }

    // ---- g2 per patch: reduce over the 16 threads sharing each patch ----
    float* p2s = uni + 2048;             // [group=t>>4][patch=t&15] == index t
    float* p2m = uni + 2048 + 256;
    p2s[t] = s2;
    p2m[t] = m2;
    __syncthreads();
    if (t < 16) {
        float s = 0.f, mx = -3.4e38f;
        #pragma unroll
        for (int g = 0; g < 16; g++) {
            s += p2s[g * 16 + t];
            mx = fmaxf(mx, p2m[g * 16 + t]);
        }
        g2s[t] = sigm(c2w0 * (s * (1.0f / 1024.0f)) + c2w1 * mx + c2b0);
    }
    __syncthreads();
    const float g2 = g2s[patch];

    // ---- apply g2 and store (same coalesced pattern as load) ----
    #pragma unroll
    for (int k = 0; k < 16; k++) {
        float4 a = v[k];
        a.x *= g2; a.y *= g2; a.z *= g2; a.w *= g2;
        const int c = cb + 4 * k;
        *(float4*)(ob + (size_t)c * plane + rowbase) = a;
    }
}

extern "C" void kernel_launch(void* const* d_in, const int* in_sizes, int n_in,
                              void* d_out, int out_size) {
    const float* x    = (const float*)d_in[0];
    const float* fc_w = (const float*)d_in[1];
    const float* fc_b = (const float*)d_in[2];
    const float* c1w  = (const float*)d_in[3];
    const float* c1b  = (const float*)d_in[4];
    const float* c2w  = (const float*)d_in[5];
    const float* c2b  = (const float*)d_in[6];
    float* out = (float*)d_out;

    // 2048 blocks: 8 batches x 64 patch-rows x 4 groups of 16 patches
    ciam_fused_kernel<<<2048, THREADS>>>(x, fc_w, fc_b, c1w, c1b, c2w, c2b, out);
}

// round 15
// speedup vs baseline: 1.6424x; 1.1701x over previous
#include <cuda_runtime.h>

// Problem constants (fixed by the dataset instance)
#define W_ 256
#define PLANE 65536
#define THREADS 128
// tile = 8 patches (64c x 4r x 32w) -> 4096 tiles, one 128-thread block each.
// 4 blocks/SM = 4 independent load/chain/store streams, narrow 4-warp barriers,
// smem-staged fc_w (no __ldg in matvec), no register spill.

__device__ __forceinline__ float sigm(float x) {
    return 1.0f / (1.0f + __expf(-x));
}

__global__ __launch_bounds__(THREADS, 4)
void ciam_n4_kernel(const float* __restrict__ x,
                    const float* __restrict__ fc_w,
                    const float* __restrict__ fc_b,
                    const float* __restrict__ c1w,
                    const float* __restrict__ c1b,
                    const float* __restrict__ c2w,
                    const float* __restrict__ c2b,
                    float* __restrict__ out)
{
    // ---- block / thread decomposition ----
    const int blk = blockIdx.x;          // 0..4095
    const int pwg = blk & 7;             // 8-patch group along W (32 px wide)
    const int ph  = (blk >> 3) & 63;     // patch row
    const int b   = blk >> 9;            // batch

    const int t  = threadIdx.x;          // 0..127
    const int p  = t & 7;                // patch
    const int r  = (t >> 3) & 3;         // row within patch
    const int cb = t >> 5;               // channel base 0..3 == warp id (c = cb + 4k)
    const int rp = t & 31;               // (r, patch)

    // ---- shared memory (~30.6 KB) ----
    __shared__ float wS[64 * 68];        // fc_w rows, stride 68
    __shared__ float fcbS[64];
    __shared__ float mxT[512];           // channel maxes [c][p] (p contiguous, 8 wide)
    __shared__ float msm[512];           // channel attention m[c][p]
    __shared__ float g1s[128];           // g1[(r,p)*4 + px]
    __shared__ float g2s[8];
    __shared__ float uni[2080];          // pm[4][520] -> gsum[512]+gmax[512]+p2s/p2m[64]

    // ---- scalar weights ----
    const float c1w0 = __ldg(c1w), c1w1 = __ldg(c1w + 1), c1b0 = __ldg(c1b);
    const float c2w0 = __ldg(c2w), c2w1 = __ldg(c2w + 1), c2b0 = __ldg(c2b);

    // ---- load tile into registers (16 x float4 / thread, coalesced: 4 lines/inst) ----
    const size_t plane = PLANE;
    const float* xb = x + (size_t)b * 64 * plane;
    float* ob = out + (size_t)b * 64 * plane;
    const int rowbase = (ph * 4 + r) * W_ + pwg * 32 + p * 4;

    float4 v[16];
    #pragma unroll
    for (int k = 0; k < 16; k++)
        v[k] = *(const float4*)(xb + (size_t)(cb + 4 * k) * plane + rowbase);

    // ---- stage fc_w -> smem (stride 68), fc_b -> smem ----
    #pragma unroll
    for (int i = 0; i < 8; i++) {
        const int j  = t + 128 * i;      // float4 chunk id, 0..1023
        const int c  = j >> 4;
        const int k4 = j & 15;
        *(float4*)(wS + c * 68 + k4 * 4) = *(const float4*)(fc_w + c * 64 + k4 * 4);
    }
    if (t < 64) fcbS[t] = fc_b[t];

    // ---- phase 1: per-(c,r,p) row max -> pm (row stride 520, conflict-free) ----
    float* pm = uni;                     // [r][c*8+p]
    #pragma unroll
    for (int k = 0; k < 16; k++) {
        float4 a = v[k];
        pm[r * 520 + (cb + 4 * k) * 8 + p] =
            fmaxf(fmaxf(a.x, a.y), fmaxf(a.z, a.w));
    }
    __syncthreads();

    // ---- phase 2: reduce over r -> mxT (float4 form, 4 per thread) ----
    {
        const int id4 = t * 4;           // 0..508, covers c*8+p
        float4 a0 = *(const float4*)(pm + id4);
        float4 a1 = *(const float4*)(pm + 520 + id4);
        float4 a2 = *(const float4*)(pm + 1040 + id4);
        float4 a3 = *(const float4*)(pm + 1560 + id4);
        float4 mr;
        mr.x = fmaxf(fmaxf(a0.x, a1.x), fmaxf(a2.x, a3.x));
        mr.y = fmaxf(fmaxf(a0.y, a1.y), fmaxf(a2.y, a3.y));
        mr.z = fmaxf(fmaxf(a0.z, a1.z), fmaxf(a2.z, a3.z));
        mr.w = fmaxf(fmaxf(a0.w, a1.w), fmaxf(a2.w, a3.w));
        *(float4*)(mxT + id4) = mr;
    }
    __syncthreads();

    // ---- phase 3: matvec m[c][p] = sigm(w[c].mx[:,p] + b[c]); 4 outputs/thread ----
    {
        const int c   = t >> 1;          // 0..63
        const int pq4 = (t & 1) * 4;     // patches 0-3 or 4-7
        float4 acc = make_float4(0.f, 0.f, 0.f, 0.f);
        #pragma unroll
        for (int kc = 0; kc < 16; kc++) {
            const float4 w4 = *(const float4*)(wS + c * 68 + kc * 4);
            const float4 m0 = *(const float4*)(mxT + (kc * 4 + 0) * 8 + pq4);
            const float4 m1 = *(const float4*)(mxT + (kc * 4 + 1) * 8 + pq4);
            acc.x += w4.x * m0.x + w4.y * m1.x;
            acc.y += w4.x * m0.y + w4.y * m1.y;
            acc.z += w4.x * m0.z + w4.y * m1.z;
            acc.w += w4.x * m0.w + w4.y * m1.w;
            const float4 m2 = *(const float4*)(mxT + (kc * 4 + 2) * 8 + pq4);
            const float4 m3 = *(const float4*)(mxT + (kc * 4 + 3) * 8 + pq4);
            acc.x += w4.z * m2.x + w4.w * m3.x;
            acc.y += w4.z * m2.y + w4.w * m3.y;
            acc.z += w4.z * m2.z + w4.w * m3.z;
            acc.w += w4.z * m2.w + w4.w * m3.w;
        }
        const float bc = fcbS[c];
        float4 mres;
        mres.x = sigm(acc.x + bc);
        mres.y = sigm(acc.y + bc);
        mres.z = sigm(acc.z + bc);
        mres.w = sigm(acc.w + bc);
        *(float4*)(msm + c * 8 + pq4) = mres;
    }
    __syncthreads();

    // ---- phase 4: apply m; per-(patch,pixel) partials over this thread's 16 channels ----
    float4 ps  = make_float4(0.f, 0.f, 0.f, 0.f);
    float4 pmx = make_float4(-3.4e38f, -3.4e38f, -3.4e38f, -3.4e38f);
    #pragma unroll
    for (int k = 0; k < 16; k++) {
        const float m = msm[(cb + 4 * k) * 8 + p];
        v[k].x *= m; v[k].y *= m; v[k].z *= m; v[k].w *= m;
        ps.x += v[k].x; ps.y += v[k].y; ps.z += v[k].z; ps.w += v[k].w;
        pmx.x = fmaxf(pmx.x, v[k].x); pmx.y = fmaxf(pmx.y, v[k].y);
        pmx.z = fmaxf(pmx.z, v[k].z); pmx.w = fmaxf(pmx.w, v[k].w);
    }
    float* gsum = uni;                   // [cb][rp*4+px] : 512 floats
    float* gmax = uni + 512;
    *(float4*)(gsum + cb * 128 + rp * 4) = ps;
    *(float4*)(gmax + cb * 128 + rp * 4) = pmx;
    __syncthreads();

    // ---- phase 5: g1 per (patch,pixel): reduce over the 4 channel-base groups ----
    {
        float s  = gsum[t] + gsum[128 + t] + gsum[256 + t] + gsum[384 + t];
        float mx = fmaxf(fmaxf(gmax[t], gmax[128 + t]), fmaxf(gmax[256 + t], gmax[384 + t]));
        g1s[t] = sigm(c1w0 * (s * (1.0f / 64.0f)) + c1w1 * mx + c1b0);
    }
    __syncthreads();

    // ---- phase 6: apply g1; per-patch partials; shuffle over r (lane bits 3-4) ----
    const float4 g1v = *(const float4*)(g1s + rp * 4);
    float s2 = 0.f, m2 = -3.4e38f;
    #pragma unroll
    for (int k = 0; k < 16; k++) {
        v[k].x *= g1v.x; v[k].y *= g1v.y; v[k].z *= g1v.z; v[k].w *= g1v.w;
        s2 += v[k].x + v[k].y + v[k].z + v[k].w;
        m2 = fmaxf(m2, fmaxf(fmaxf(v[k].x, v[k].y), fmaxf(v[k].z, v[k].w)));
    }
    s2 += __shfl_xor_sync(0xffffffffu, s2, 8);
    m2 = fmaxf(m2, __shfl_xor_sync(0xffffffffu, m2, 8));
    s2 += __shfl_xor_sync(0xffffffffu, s2, 16);
    m2 = fmaxf(m2, __shfl_xor_sync(0xffffffffu, m2, 16));
    float* p2s = uni + 1024;             // [cb][p] : 32 floats
    float* p2m = uni + 1056;
    if (rp < 8) { p2s[cb * 8 + p] = s2; p2m[cb * 8 + p] = m2; }
    __syncthreads();

    // ---- phase 7: g2 per patch (4 cb contributions each) ----
    if (t < 8) {
        float s = 0.f, mx = -3.4e38f;
        #pragma unroll
        for (int g = 0; g < 4; g++) {
            s += p2s[g * 8 + t];
            mx = fmaxf(mx, p2m[g * 8 + t]);
        }
        g2s[t] = sigm(c2w0 * (s * (1.0f / 1024.0f)) + c2w1 * mx + c2b0);
    }
    __syncthreads();
    const float g2 = g2s[p];

    // ---- phase 8: apply g2 and store (same coalesced pattern as load) ----
    #pragma unroll
    for (int k = 0; k < 16; k++) {
        float4 a = v[k];
        a.x *= g2; a.y *= g2; a.z *= g2; a.w *= g2;
        *(float4*)(ob + (size_t)(cb + 4 * k) * plane + rowbase) = a;
    }
}

extern "C" void kernel_launch(void* const* d_in, const int* in_sizes, int n_in,
                              void* d_out, int out_size) {
    const float* x    = (const float*)d_in[0];
    const float* fc_w = (const float*)d_in[1];
    const float* fc_b = (const float*)d_in[2];
    const float* c1w  = (const float*)d_in[3];
    const float* c1b  = (const float*)d_in[4];
    const float* c2w  = (const float*)d_in[5];
    const float* c2b  = (const float*)d_in[6];
    float* out = (float*)d_out;

    // 4096 blocks: 8 batches x 64 patch-rows x 8 groups of 8 patches
    ciam_n4_kernel<<<4096, THREADS>>>(x, fc_w, fc_b, c1w, c1b, c2w, c2b, out);
}